// round 2
// baseline (speedup 1.0000x reference)
#include <cuda_runtime.h>
#include <cuda_bf16.h>
#include <cstdint>

// VectorQuantStraightThrough: z_e [32,4096,64] f32, emb [512,64] f32
// Reference (fp32, XLA): d2 = ||z||^2 - 2 z.e + ||e||^2, argmin_k, gather.
// CRITICAL: replicate the reference's fp32 rounding at scale ||z||^2 ~ 64:
//   d2_k = fl( fl( z2 - fl(2*dot_k) ) + e2_k )
// A per-row constant error in z2 is argmin-invariant (grid-multiple shift).

#define NROWS (32 * 4096)   // 131072
#define DDIM  64
#define KCB   512

#define TPB     256
#define ROWS_PER_THREAD 2
#define GRID    (NROWS / (TPB * ROWS_PER_THREAD))   // 256

// packed f32x2 helpers (Blackwell sm_103a)
#define FFMA2(acc, a, b) \
    asm("fma.rn.f32x2 %0, %1, %2, %3;" : "=l"(acc) : "l"(a), "l"(b), "l"(acc))
#define FADD2(out, a, b) \
    asm("add.rn.f32x2 %0, %1, %2;" : "=l"(out) : "l"(a), "l"(b))
#define UNPACK2(lo, hi, in) \
    asm("mov.b64 {%0, %1}, %2;" : "=f"(lo), "=f"(hi) : "l"(in))

__global__ __launch_bounds__(TPB, 1)
void vq_argmin_gather_kernel(const float* __restrict__ z,
                             const float* __restrict__ emb,
                             float* __restrict__ out,
                             long long out_size) {
    extern __shared__ float smem[];
    float* se    = smem;              // [K][D] codebook
    float* sbias = smem + KCB * DDIM; // [K] ||e_k||^2

    const int tid = threadIdx.x;

    // ---- stage codebook into smem (128 KB), vectorized ----
    {
        const float4* g4 = (const float4*)emb;
        float4* s4 = (float4*)se;
        const int n4 = KCB * DDIM / 4;  // 8192
        #pragma unroll 4
        for (int i = tid; i < n4; i += TPB) s4[i] = g4[i];
    }
    __syncthreads();

    // ---- per-code bias ||e_k||^2 ----
    for (int k = tid; k < KCB; k += TPB) {
        const float* e = se + k * DDIM;
        float s = 0.f;
        #pragma unroll
        for (int d = 0; d < DDIM; d++) s = fmaf(e[d], e[d], s);
        sbias[k] = s;
    }
    __syncthreads();

    // ---- load this thread's two z rows into packed f32x2 registers ----
    const long long n0 = (long long)blockIdx.x * (TPB * ROWS_PER_THREAD) + tid;
    const long long n1 = n0 + TPB;

    unsigned long long z0[DDIM / 2], z1[DDIM / 2];
    {
        const ulonglong2* p0 = (const ulonglong2*)(z + n0 * DDIM);
        const ulonglong2* p1 = (const ulonglong2*)(z + n1 * DDIM);
        #pragma unroll
        for (int j = 0; j < DDIM / 4; j++) {
            ulonglong2 a = p0[j]; z0[2 * j] = a.x; z0[2 * j + 1] = a.y;
            ulonglong2 b = p1[j]; z1[2 * j] = b.x; z1[2 * j + 1] = b.y;
        }
    }

    // ---- per-row ||z||^2 (constant-shift errors are argmin-invariant) ----
    float z2r0, z2r1;
    {
        unsigned long long s0a = 0ull, s0b = 0ull, s1a = 0ull, s1b = 0ull;
        #pragma unroll
        for (int j = 0; j < DDIM / 4; j++) {
            FFMA2(s0a, z0[2 * j],     z0[2 * j]);
            FFMA2(s0b, z0[2 * j + 1], z0[2 * j + 1]);
            FFMA2(s1a, z1[2 * j],     z1[2 * j]);
            FFMA2(s1b, z1[2 * j + 1], z1[2 * j + 1]);
        }
        FADD2(s0a, s0a, s0b);
        FADD2(s1a, s1a, s1b);
        float lo, hi;
        UNPACK2(lo, hi, s0a); z2r0 = __fadd_rn(lo, hi);
        UNPACK2(lo, hi, s1a); z2r1 = __fadd_rn(lo, hi);
    }

    float best0 = 3.4e38f, best1 = 3.4e38f;
    int   idx0 = 0, idx1 = 0;

    // ---- main loop over 512 codes ----
    for (int k = 0; k < KCB; k++) {
        const ulonglong2* ek = (const ulonglong2*)(se + k * DDIM);
        unsigned long long a00 = 0ull, a01 = 0ull, a10 = 0ull, a11 = 0ull;
        #pragma unroll
        for (int j = 0; j < DDIM / 4; j++) {
            ulonglong2 ev = ek[j];   // broadcast LDS.128
            FFMA2(a00, z0[2 * j],     ev.x);
            FFMA2(a01, z0[2 * j + 1], ev.y);
            FFMA2(a10, z1[2 * j],     ev.x);
            FFMA2(a11, z1[2 * j + 1], ev.y);
        }
        FADD2(a00, a00, a01);
        FADD2(a10, a10, a11);
        float lo, hi;
        UNPACK2(lo, hi, a00); const float dot0 = __fadd_rn(lo, hi);
        UNPACK2(lo, hi, a10); const float dot1 = __fadd_rn(lo, hi);

        const float bk = sbias[k];
        // Replicate reference rounding: (z2 - 2*dot) + e2, all fp32, no FMA.
        const float d0 = __fadd_rn(__fsub_rn(z2r0, __fmul_rn(2.f, dot0)), bk);
        const float d1 = __fadd_rn(__fsub_rn(z2r1, __fmul_rn(2.f, dot1)), bk);
        if (d0 < best0) { best0 = d0; idx0 = k; }   // strict < == first-index tiebreak
        if (d1 < best1) { best1 = d1; idx1 = k; }
    }

    // ---- epilogue: gather z_q = emb[idx] from smem, write outputs ----
    const long long ND = (long long)NROWS * DDIM;   // 8388608

    const float4* e0 = (const float4*)(se + idx0 * DDIM);
    const float4* e1 = (const float4*)(se + idx1 * DDIM);

    if (out_size >= ND) {
        float4* o0 = (float4*)(out + n0 * DDIM);
        float4* o1 = (float4*)(out + n1 * DDIM);
        #pragma unroll
        for (int j = 0; j < DDIM / 4; j++) { o0[j] = e0[j]; o1[j] = e1[j]; }
    }
    if (out_size >= 2 * ND) {   // second copy (z_q after z_q_st)
        float4* o0 = (float4*)(out + ND + n0 * DDIM);
        float4* o1 = (float4*)(out + ND + n1 * DDIM);
        #pragma unroll
        for (int j = 0; j < DDIM / 4; j++) { o0[j] = e0[j]; o1[j] = e1[j]; }
    }
    // indices region (as float — values 0..511 exact in f32)
    if (out_size >= 2 * ND + NROWS) {
        out[2 * ND + n0] = (float)idx0;
        out[2 * ND + n1] = (float)idx1;
    } else if (out_size == ND + NROWS) {
        out[ND + n0] = (float)idx0;
        out[ND + n1] = (float)idx1;
    } else if (out_size == NROWS) {  // indices-only layout
        out[n0] = (float)idx0;
        out[n1] = (float)idx1;
    }
}

extern "C" void kernel_launch(void* const* d_in, const int* in_sizes, int n_in,
                              void* d_out, int out_size) {
    // metadata order: z_e (8388608 elems), emb (32768 elems). Be robust to swap.
    const float* z   = (const float*)d_in[0];
    const float* emb = (const float*)d_in[1];
    if (n_in >= 2 && in_sizes[0] == KCB * DDIM && in_sizes[1] == NROWS * DDIM) {
        z   = (const float*)d_in[1];
        emb = (const float*)d_in[0];
    }

    const int smem_bytes = (KCB * DDIM + KCB) * (int)sizeof(float);  // 133120
    cudaFuncSetAttribute(vq_argmin_gather_kernel,
                         cudaFuncAttributeMaxDynamicSharedMemorySize, smem_bytes);

    vq_argmin_gather_kernel<<<GRID, TPB, smem_bytes>>>(
        z, emb, (float*)d_out, (long long)out_size);
}